// round 6
// baseline (speedup 1.0000x reference)
#include <cuda_runtime.h>

// ---------------- problem constants ----------------
constexpr int Bq  = 128;
constexpr int Tq  = 512;
constexpr int INq = 3;
constexpr int Aq  = 77;
constexpr int Hq  = 512;
constexpr int KWq = 10;
constexpr int KMq = 20;
constexpr int Uq  = 64;
constexpr int OUTq = 121;           // 6*KM + 1
constexpr int NCTA = 128;

// ---------------- persistent device state (transposed [feat][batch]) ----------------
__device__ float g_h1[2][Hq * Bq];
__device__ float g_h2[2][Hq * Bq];
__device__ float g_c1[Hq * Bq];
__device__ float g_c2[Hq * Bq];
__device__ float g_w[Aq * Bq];          // attention window w_t, [a][b]
__device__ float g_kappa[Bq * KWq];     // [b][k]
__device__ float g_h2all[Tq][Hq * Bq];  // all h2 states for deferred fc2 (134 MB)
__device__ float g_raw[Tq][128 * Bq];   // raw fc2 outputs [t][o][b] (o padded to 128)
__device__ unsigned g_bar_cnt;
__device__ unsigned g_bar_gen;

// ---------------- helpers ----------------
__device__ __forceinline__ unsigned long long pk2(float v) {
    unsigned long long r; unsigned u = __float_as_uint(v);
    asm("mov.b64 %0, {%1, %1};" : "=l"(r) : "r"(u));
    return r;
}
__device__ __forceinline__ void fma2(unsigned long long& d, unsigned long long a, unsigned long long b) {
    asm("fma.rn.f32x2 %0, %1, %2, %0;" : "+l"(d) : "l"(a), "l"(b));
}
__device__ __forceinline__ float2 up2(unsigned long long v) {
    unsigned lo, hi;
    asm("mov.b64 {%0, %1}, %2;" : "=r"(lo), "=r"(hi) : "l"(v));
    float2 f; f.x = __uint_as_float(lo); f.y = __uint_as_float(hi); return f;
}
__device__ __forceinline__ float sigf(float x) { return 1.f / (1.f + expf(-x)); }

// Grid-wide sense barrier. All 128 CTAs co-resident (one wave). Release side:
// every thread fences its own global stores (gpu-scope fence also flushes L1
// on Blackwell via CCTL.IVALL); acquire side: leader fences after observing
// the generation flip, then CTA syncthreads orders everyone's reads after it.
__device__ __forceinline__ void grid_barrier() {
    __threadfence();
    __syncthreads();
    if (threadIdx.x == 0) {
        unsigned gen = *(volatile unsigned*)&g_bar_gen;
        if (atomicAdd(&g_bar_cnt, 1u) == (unsigned)gridDim.x - 1u) {
            *(volatile unsigned*)&g_bar_cnt = 0u;
            __threadfence();
            *(volatile unsigned*)&g_bar_gen = gen + 1u;
        } else {
            while (*(volatile unsigned*)&g_bar_gen == gen) { __nanosleep(32); }
        }
        __threadfence();
    }
    __syncthreads();
}

// ---------------- init ----------------
__global__ void k_init() {
    int i = blockIdx.x * 256 + threadIdx.x;
    if (i < Hq * Bq) { g_h1[0][i] = 0.f; g_h2[0][i] = 0.f; g_c1[i] = 0.f; g_c2[i] = 0.f; }
    if (i < Aq * Bq)  g_w[i] = 0.f;
    if (i < Bq * KWq) g_kappa[i] = 0.f;
    if (i == 0) { g_bar_cnt = 0u; g_bar_gen = 0u; }
}

// ---------------- one LSTM phase (gates GEMM + cell update) ----------------
// CTA owns 4 hidden units = 16 gate rows. Weights live in smem w_s [nch*64][16]
// (zero-padded past K). Input regions: [0,3)=x, [3,80)=g_w, [80,KA)=hA, [KA,K)=hB.
__device__ __forceinline__ void lstm_phase(
    int t, int unit0, int tid,
    const float* __restrict__ x,
    const float* __restrict__ w_s,
    const float* __restrict__ bias_s,
    const float* __restrict__ hA,
    const float* __restrict__ hB,
    float* __restrict__ h_out,
    float* __restrict__ c_st,
    float* __restrict__ h2all,
    int KA, int K, int nch,
    float* __restrict__ v_s, float* __restrict__ z_s)
{
    const int rp = tid & 7;           // row pair -> rows 2rp, 2rp+1
    const int ty = (tid >> 3) & 15;   // batch group
    const int tz = tid >> 7;          // k half
    const int b0 = ty * 8;

    unsigned long long a0=0,a1=0,a2=0,a3=0,a4=0,a5=0,a6=0,a7=0;

    for (int c = 0; c < nch; ++c) {
        const int kk0 = c * 64;
        // ---- stage inputs into v_s [64][128] ----
        if (kk0 >= 80 && kk0 + 64 <= KA) {
            const float4* sp = (const float4*)(hA + (kk0 - 80) * Bq);
            float4* dp = (float4*)v_s;
            #pragma unroll
            for (int i = 0; i < 8; ++i) dp[tid + i * 256] = sp[tid + i * 256];
        } else if (hB != nullptr && kk0 >= KA && kk0 + 64 <= K) {
            const float4* sp = (const float4*)(hB + (kk0 - KA) * Bq);
            float4* dp = (float4*)v_s;
            #pragma unroll
            for (int i = 0; i < 8; ++i) dp[tid + i * 256] = sp[tid + i * 256];
        } else {
            for (int idx = tid; idx < 64 * Bq; idx += 256) {
                int k = idx >> 7, b = idx & (Bq - 1);
                int kk = kk0 + k;
                float v = 0.f;
                if (kk < INq)             v = x[(b * Tq + t) * INq + kk];
                else if (kk < 80)         v = g_w[(kk - INq) * Bq + b];
                else if (kk < KA)         v = hA[(kk - 80) * Bq + b];
                else if (hB && kk < K)    v = hB[(kk - KA) * Bq + b];
                v_s[k * Bq + b] = v;
            }
        }
        __syncthreads();
        const float* wrow = w_s + (kk0 + tz * 32) * 16 + rp * 2;
        const float* vrow = v_s + (tz * 32) * Bq + b0;
        #pragma unroll
        for (int k2 = 0; k2 < 32; ++k2) {
            float2 wv = *(const float2*)(wrow + k2 * 16);
            unsigned long long wp0 = pk2(wv.x), wp1 = pk2(wv.y);
            ulonglong2 p0 = *(const ulonglong2*)(vrow + k2 * Bq);
            ulonglong2 p1 = *(const ulonglong2*)(vrow + k2 * Bq + 4);
            fma2(a0, p0.x, wp0); fma2(a1, p0.y, wp0);
            fma2(a2, p1.x, wp0); fma2(a3, p1.y, wp0);
            fma2(a4, p0.x, wp1); fma2(a5, p0.y, wp1);
            fma2(a6, p1.x, wp1); fma2(a7, p1.y, wp1);
        }
        __syncthreads();
    }
    // ---- split-K reduction into z_s [16][128] ----
    const int r0 = rp * 2, r1 = r0 + 1;
    float2 f;
    if (tz == 1) {
        f = up2(a0); z_s[r0*Bq+b0+0]=f.x; z_s[r0*Bq+b0+1]=f.y;
        f = up2(a1); z_s[r0*Bq+b0+2]=f.x; z_s[r0*Bq+b0+3]=f.y;
        f = up2(a2); z_s[r0*Bq+b0+4]=f.x; z_s[r0*Bq+b0+5]=f.y;
        f = up2(a3); z_s[r0*Bq+b0+6]=f.x; z_s[r0*Bq+b0+7]=f.y;
        f = up2(a4); z_s[r1*Bq+b0+0]=f.x; z_s[r1*Bq+b0+1]=f.y;
        f = up2(a5); z_s[r1*Bq+b0+2]=f.x; z_s[r1*Bq+b0+3]=f.y;
        f = up2(a6); z_s[r1*Bq+b0+4]=f.x; z_s[r1*Bq+b0+5]=f.y;
        f = up2(a7); z_s[r1*Bq+b0+6]=f.x; z_s[r1*Bq+b0+7]=f.y;
    }
    __syncthreads();
    if (tz == 0) {
        float bias0 = bias_s[r0];
        float bias1 = bias_s[r1];
        f = up2(a0); z_s[r0*Bq+b0+0]+=f.x+bias0; z_s[r0*Bq+b0+1]+=f.y+bias0;
        f = up2(a1); z_s[r0*Bq+b0+2]+=f.x+bias0; z_s[r0*Bq+b0+3]+=f.y+bias0;
        f = up2(a2); z_s[r0*Bq+b0+4]+=f.x+bias0; z_s[r0*Bq+b0+5]+=f.y+bias0;
        f = up2(a3); z_s[r0*Bq+b0+6]+=f.x+bias0; z_s[r0*Bq+b0+7]+=f.y+bias0;
        f = up2(a4); z_s[r1*Bq+b0+0]+=f.x+bias1; z_s[r1*Bq+b0+1]+=f.y+bias1;
        f = up2(a5); z_s[r1*Bq+b0+2]+=f.x+bias1; z_s[r1*Bq+b0+3]+=f.y+bias1;
        f = up2(a6); z_s[r1*Bq+b0+4]+=f.x+bias1; z_s[r1*Bq+b0+5]+=f.y+bias1;
        f = up2(a7); z_s[r1*Bq+b0+6]+=f.x+bias1; z_s[r1*Bq+b0+7]+=f.y+bias1;
    }
    __syncthreads();
    // ---- pointwise LSTM cell (4 units x 128 batch) ----
    #pragma unroll
    for (int it = 0; it < 2; ++it) {
        int idx = tid + it * 256;
        int au = idx >> 7;        // 0..3
        int b  = idx & 127;
        float zi = z_s[au*Bq+b], zf = z_s[(4+au)*Bq+b];
        float zg = z_s[(8+au)*Bq+b], zo = z_s[(12+au)*Bq+b];
        int j = unit0 + au;
        float cold = c_st[j * Bq + b];
        float cn = sigf(zf) * cold + sigf(zi) * tanhf(zg);
        float hn = sigf(zo) * tanhf(cn);
        c_st[j * Bq + b] = cn;
        h_out[j * Bq + b] = hn;
        if (h2all) h2all[j * Bq + b] = hn;
    }
}

// ---------------- attention phase: CTA handles batch b = blockIdx.x ----------------
__device__ __forceinline__ void attn_phase(
    int b, int tid,
    const float* __restrict__ W_abk, const float* __restrict__ b_abk,
    const float* __restrict__ c_seq, const float* __restrict__ h1,
    float* __restrict__ s)
{
    float* h_s   = s;           // 512
    float* abk_s = s + 512;     // 32
    float* al    = s + 544;     // 10
    float* be    = s + 556;     // 10
    float* ka    = s + 568;     // 10
    float* phi   = s + 584;     // 64

    #pragma unroll
    for (int k = tid; k < Hq; k += 256) h_s[k] = h1[k * Bq + b];
    __syncthreads();

    int lane = tid & 31, wrp = tid >> 5;
    for (int r = wrp; r < 3 * KWq; r += 8) {
        float sm = 0.f;
        const float* wr = W_abk + r * Hq;
        for (int k = lane; k < Hq; k += 32) sm += h_s[k] * wr[k];
        #pragma unroll
        for (int o = 16; o; o >>= 1) sm += __shfl_xor_sync(0xffffffffu, sm, o);
        if (lane == 0) abk_s[r] = sm + b_abk[r];
    }
    __syncthreads();
    if (tid < KWq) {
        float kap = g_kappa[b * KWq + tid] + expf(abk_s[2 * KWq + tid]);
        g_kappa[b * KWq + tid] = kap;
        al[tid] = expf(abk_s[tid]);
        be[tid] = expf(abk_s[KWq + tid]);
        ka[tid] = kap;
    }
    __syncthreads();
    if (tid < Uq) {
        float u = (float)tid;
        float sm = 0.f;
        #pragma unroll
        for (int k = 0; k < KWq; ++k) {
            float d = ka[k] - u;
            sm += al[k] * expf(-be[k] * d * d);
        }
        phi[tid] = sm;
    }
    __syncthreads();
    if (tid < Aq) {
        float sm = 0.f;
        for (int u = 0; u < Uq; ++u) sm += phi[u] * c_seq[(b * Uq + u) * Aq + tid];
        g_w[tid * Bq + b] = sm;
    }
}

// ---------------- persistent main kernel: whole T=512 scan ----------------
// smem layout (floats): w1_s[640*16] | w2_s[1152*16] | v_s[64*128] | z_s[16*128] | bs1[16] | bs2[16]
constexpr int SM_W1 = 0;
constexpr int SM_W2 = SM_W1 + 640 * 16;     // 10240
constexpr int SM_V  = SM_W2 + 1152 * 16;    // 28672
constexpr int SM_Z  = SM_V + 64 * Bq;       // 36864
constexpr int SM_B1 = SM_Z + 16 * Bq;       // 38912
constexpr int SM_B2 = SM_B1 + 16;           // 38928
constexpr int SM_TOT_FLOATS = SM_B2 + 16;   // 38944
constexpr int SM_BYTES = SM_TOT_FLOATS * 4; // 155776

__global__ void __launch_bounds__(256, 1) k_main(
    const float* __restrict__ x, const float* __restrict__ c_seq,
    const float* __restrict__ Wih1, const float* __restrict__ Whh1,
    const float* __restrict__ bih1, const float* __restrict__ bhh1,
    const float* __restrict__ Wih2, const float* __restrict__ Whh2,
    const float* __restrict__ bih2, const float* __restrict__ bhh2,
    const float* __restrict__ W_abk, const float* __restrict__ b_abk)
{
    extern __shared__ float smem[];
    float* w1_s = smem + SM_W1;
    float* w2_s = smem + SM_W2;
    float* v_s  = smem + SM_V;
    float* z_s  = smem + SM_Z;
    float* bs1  = smem + SM_B1;
    float* bs2  = smem + SM_B2;

    const int tid = threadIdx.x;
    const int unit0 = blockIdx.x * 4;
    const int myb = blockIdx.x;          // batch element for attention phase

    // ---- one-time weight preload into smem (zero-padded past K) ----
    for (int idx = tid; idx < 640 * 16; idx += 256) {
        int i = idx & 15, kk = idx >> 4;
        int r = ((i >> 2) * Hq) + unit0 + (i & 3);
        float wv = 0.f;
        if (kk < 80)      wv = Wih1[r * 80 + kk];
        else if (kk < 592) wv = Whh1[r * Hq + (kk - 80)];
        w1_s[idx] = wv;
    }
    for (int idx = tid; idx < 1152 * 16; idx += 256) {
        int i = idx & 15, kk = idx >> 4;
        int r = ((i >> 2) * Hq) + unit0 + (i & 3);
        float wv = 0.f;
        if (kk < 592)       wv = Wih2[r * 592 + kk];
        else if (kk < 1104) wv = Whh2[r * Hq + (kk - 592)];
        w2_s[idx] = wv;
    }
    if (tid < 16) {
        int r = ((tid >> 2) * Hq) + unit0 + (tid & 3);
        bs1[tid] = bih1[r] + bhh1[r];
        bs2[tid] = bih2[r] + bhh2[r];
    }
    __syncthreads();

    for (int t = 0; t < Tq; ++t) {
        const int src = t & 1, dst = src ^ 1;
        // LSTM1: inputs [x | w_{t-1} | h1_src]
        lstm_phase(t, unit0, tid, x, w1_s, bs1,
                   g_h1[src], nullptr,
                   g_h1[dst], g_c1, nullptr,
                   592, 592, 10, v_s, z_s);
        grid_barrier();
        // Attention on fresh h1
        attn_phase(myb, tid, W_abk, b_abk, c_seq, g_h1[dst], v_s);
        grid_barrier();
        // LSTM2: inputs [x | w_t | h1_new | h2_src]
        lstm_phase(t, unit0, tid, x, w2_s, bs2,
                   g_h1[dst], g_h2[src],
                   g_h2[dst], g_c2, g_h2all[t],
                   592, 1104, 18, v_s, z_s);
        // No barrier needed before next LSTM1: it writes g_h1[src] (not read
        // by any in-flight LSTM2) and reads only data already fenced at the
        // two barriers above. Cross-step h2/w hazards are covered by the
        // next step's barriers.
        __syncthreads();
    }
}

// ---------------- deferred fc2: grid (8 out-groups, 512 timesteps) ----------------
__global__ void __launch_bounds__(256) k_fc2(const float* __restrict__ Wf, const float* __restrict__ bf)
{
    __shared__ float v_s[64][Bq];
    __shared__ float w_s[64][16];
    const int tid = threadIdx.x;
    const int tx = tid & 15, ty = tid >> 4, b0 = ty * 8;
    const int t = blockIdx.y, og = blockIdx.x;
    const int o = og * 16 + tx;

    unsigned long long a0=0,a1=0,a2=0,a3=0;
    for (int c = 0; c < 8; ++c) {
        const int kk0 = c * 64;
        const float4* sp = (const float4*)(g_h2all[t] + kk0 * Bq);
        float4* dp = (float4*)(&v_s[0][0]);
        #pragma unroll
        for (int i = 0; i < 8; ++i) dp[tid + i * 256] = sp[tid + i * 256];
        {
            int i = tid & 15, kq = tid >> 4;
            int oo = og * 16 + i;
            float4 wv = make_float4(0.f, 0.f, 0.f, 0.f);
            if (oo < OUTq) wv = *(const float4*)(Wf + oo * Hq + kk0 + kq * 4);
            w_s[kq * 4 + 0][i] = wv.x; w_s[kq * 4 + 1][i] = wv.y;
            w_s[kq * 4 + 2][i] = wv.z; w_s[kq * 4 + 3][i] = wv.w;
        }
        __syncthreads();
        #pragma unroll
        for (int k = 0; k < 64; ++k) {
            unsigned long long wp = pk2(w_s[k][tx]);
            ulonglong2 p0 = *(const ulonglong2*)&v_s[k][b0];
            ulonglong2 p1 = *(const ulonglong2*)&v_s[k][b0 + 4];
            fma2(a0, p0.x, wp); fma2(a1, p0.y, wp);
            fma2(a2, p1.x, wp); fma2(a3, p1.y, wp);
        }
        __syncthreads();
    }
    if (o < OUTq) {
        float bias = bf[o];
        float* dstp = &g_raw[t][o * Bq + b0];
        float2 f;
        f = up2(a0); dstp[0] = f.x + bias; dstp[1] = f.y + bias;
        f = up2(a1); dstp[2] = f.x + bias; dstp[3] = f.y + bias;
        f = up2(a2); dstp[4] = f.x + bias; dstp[5] = f.y + bias;
        f = up2(a3); dstp[6] = f.x + bias; dstp[7] = f.y + bias;
    }
}

// ---------------- MDN post-processing -> d_out (7 flattened segments) ----------------
__global__ void __launch_bounds__(256) k_post(float* __restrict__ out)
{
    int idx = blockIdx.x * 256 + threadIdx.x;
    if (idx >= Bq * Tq) return;
    int b = idx & (Bq - 1);
    int t = idx >> 7;
    const float* raw = g_raw[t];
    const size_t BT = (size_t)Bq * Tq;
    const size_t base = (size_t)b * Tq + t;

    float v[KMq];
    float m = -1e30f;
    #pragma unroll
    for (int k = 0; k < KMq; ++k) { v[k] = raw[k * Bq + b]; m = fmaxf(m, v[k]); }
    float s = 0.f;
    #pragma unroll
    for (int k = 0; k < KMq; ++k) { v[k] = expf(v[k] - m); s += v[k]; }
    float inv = 1.f / s;
    #pragma unroll
    for (int k = 0; k < KMq; ++k) out[base * KMq + k] = v[k] * inv;

    float* mu1 = out + BT * KMq;
    float* mu2 = out + 2 * BT * KMq;
    float* s1  = out + 3 * BT * KMq;
    float* s2  = out + 4 * BT * KMq;
    float* co  = out + 5 * BT * KMq;
    #pragma unroll
    for (int k = 0; k < KMq; ++k) {
        mu1[base * KMq + k] = raw[(KMq + k) * Bq + b];
        mu2[base * KMq + k] = raw[(2 * KMq + k) * Bq + b];
        s1[base * KMq + k]  = expf(raw[(3 * KMq + k) * Bq + b]);
        s2[base * KMq + k]  = expf(raw[(4 * KMq + k) * Bq + b]);
        co[base * KMq + k]  = tanhf(raw[(5 * KMq + k) * Bq + b]);
    }
    out[6 * BT * KMq + base] = sigf(raw[(6 * KMq) * Bq + b]);
}

// ---------------- launch ----------------
extern "C" void kernel_launch(void* const* d_in, const int* in_sizes, int n_in,
                              void* d_out, int out_size)
{
    (void)in_sizes; (void)n_in; (void)out_size;
    const float* x     = (const float*)d_in[0];
    const float* c_seq = (const float*)d_in[1];
    const float* Wih1  = (const float*)d_in[2];
    const float* Whh1  = (const float*)d_in[3];
    const float* bih1  = (const float*)d_in[4];
    const float* bhh1  = (const float*)d_in[5];
    const float* Wih2  = (const float*)d_in[6];
    const float* Whh2  = (const float*)d_in[7];
    const float* bih2  = (const float*)d_in[8];
    const float* bhh2  = (const float*)d_in[9];
    const float* W_abk = (const float*)d_in[10];
    const float* b_abk = (const float*)d_in[11];
    const float* W_fc2 = (const float*)d_in[12];
    const float* b_fc2 = (const float*)d_in[13];

    static bool attr_done = false;
    if (!attr_done) {
        cudaFuncSetAttribute(k_main, cudaFuncAttributeMaxDynamicSharedMemorySize, SM_BYTES);
        attr_done = true;
    }

    k_init<<<256, 256>>>();
    k_main<<<NCTA, 256, SM_BYTES>>>(x, c_seq, Wih1, Whh1, bih1, bhh1,
                                    Wih2, Whh2, bih2, bhh2, W_abk, b_abk);
    k_fc2<<<dim3(8, Tq), 256>>>(W_fc2, b_fc2);
    k_post<<<256, 256>>>((float*)d_out);
}

// round 7
// speedup vs baseline: 1.9735x; 1.9735x over previous
#include <cuda_runtime.h>

// ---------------- problem constants ----------------
constexpr int Bq  = 128;
constexpr int Tq  = 512;
constexpr int Aq  = 77;
constexpr int Hq  = 512;
constexpr int KWq = 10;
constexpr int KMq = 20;
constexpr int Uq  = 64;
constexpr int OUTq = 121;           // 6*KM + 1
constexpr int NCTA = 128;

// Padded K layout: [x:4 | w:80 | h1:512 | h2:512 | pad]
// lstm1: K=596 -> 10 chunks (640).  lstm2: K=1108 -> 18 chunks (1152).

// ---------------- persistent device state (transposed [feat][batch]) ----------------
__device__ float g_h1[2][Hq * Bq];
__device__ float g_h2[2][Hq * Bq];
__device__ float g_c1[Hq * Bq];
__device__ float g_c2[Hq * Bq];
__device__ float g_wp[80 * Bq];         // attention window, padded to 80 rows
__device__ float g_xT[Tq][4 * Bq];      // x transposed+padded: [t][k(4)][b]
__device__ float g_zero[Bq];            // zero row for padding chunks
__device__ float g_kappa[Bq * KWq];     // [b][k]
__device__ float g_h2all[Tq][Hq * Bq];  // all h2 states for deferred fc2
__device__ float g_raw[Tq][128 * Bq];   // raw fc2 outputs [t][o][b]
__device__ unsigned g_bar_cnt;
__device__ unsigned g_bar_gen;

// ---------------- helpers ----------------
__device__ __forceinline__ unsigned long long pk2(float v) {
    unsigned long long r; unsigned u = __float_as_uint(v);
    asm("mov.b64 %0, {%1, %1};" : "=l"(r) : "r"(u));
    return r;
}
__device__ __forceinline__ void fma2(unsigned long long& d, unsigned long long a, unsigned long long b) {
    asm("fma.rn.f32x2 %0, %1, %2, %0;" : "+l"(d) : "l"(a), "l"(b));
}
__device__ __forceinline__ float2 up2(unsigned long long v) {
    unsigned lo, hi;
    asm("mov.b64 {%0, %1}, %2;" : "=r"(lo), "=r"(hi) : "l"(v));
    float2 f; f.x = __uint_as_float(lo); f.y = __uint_as_float(hi); return f;
}
__device__ __forceinline__ float sigf(float x) { return 1.f / (1.f + expf(-x)); }

// Grid-wide barrier, cooperative-groups style: bar.sync establishes CTA-level
// happens-before, thread 0's cumulative gpu-scope fence releases all of the
// CTA's prior stores; waiters acquire the generation then fence + bar.sync.
__device__ __forceinline__ void grid_barrier() {
    __syncthreads();
    if (threadIdx.x == 0) {
        asm volatile("fence.acq_rel.gpu;" ::: "memory");
        unsigned gen = g_bar_gen;   // same-thread coherence: >= last acquired value
        if (atomicAdd(&g_bar_cnt, 1u) == (unsigned)NCTA - 1u) {
            g_bar_cnt = 0u;
            asm volatile("fence.acq_rel.gpu;" ::: "memory");
            atomicExch(&g_bar_gen, gen + 1u);     // fence+relaxed = release
        } else {
            unsigned cur;
            do {
                asm volatile("ld.acquire.gpu.u32 %0, [%1];"
                             : "=r"(cur) : "l"(&g_bar_gen));
            } while (cur == gen);
        }
        asm volatile("fence.acq_rel.gpu;" ::: "memory");
    }
    __syncthreads();
}

// ---------------- init: zero state + transpose x ----------------
__global__ void k_init(const float* __restrict__ x) {
    int i = blockIdx.x * 256 + threadIdx.x;
    if (i < Tq * 4 * Bq) {                     // 262144 threads cover this
        int t = i >> 9, r = i & 511, k = r >> 7, b = r & 127;
        g_xT[t][r] = (k < 3) ? x[(b * Tq + t) * 3 + k] : 0.f;
    }
    if (i < Hq * Bq) { g_h1[0][i] = 0.f; g_h2[0][i] = 0.f; g_c1[i] = 0.f; g_c2[i] = 0.f; }
    if (i < 80 * Bq)  g_wp[i] = 0.f;
    if (i < Bq)       g_zero[i] = 0.f;
    if (i < Bq * KWq) g_kappa[i] = 0.f;
    if (i == 0) { g_bar_cnt = 0u; g_bar_gen = 0u; }
}

// ---------------- async chunk stager: warp w copies rows {w, w+8, ...} ----------------
__device__ __forceinline__ void stage_chunk(
    float* __restrict__ vbuf, int kk0, const float* __restrict__ xt,
    const float* __restrict__ hA, const float* __restrict__ hB, int tid)
{
    const int lane = tid & 31, w = tid >> 5;
    #pragma unroll
    for (int it = 0; it < 8; ++it) {
        int k = it * 8 + w;
        int kk = kk0 + k;
        const float* src;                 // warp-uniform branch
        if (kk < 4)                           src = xt + kk * Bq;
        else if (kk < 84)                     src = g_wp + (kk - 4) * Bq;
        else if (kk < 596)                    src = hA + (kk - 84) * Bq;
        else if (hB != nullptr && kk < 1108)  src = hB + (kk - 596) * Bq;
        else                                  src = g_zero;
        unsigned daddr = (unsigned)__cvta_generic_to_shared(vbuf + k * Bq + lane * 4);
        asm volatile("cp.async.cg.shared.global [%0], [%1], 16;"
                     :: "r"(daddr), "l"(src + lane * 4) : "memory");
    }
    asm volatile("cp.async.commit_group;" ::: "memory");
}

// ---------------- one LSTM phase: double-buffered gates GEMM + cell update ----------------
__device__ __forceinline__ void lstm_phase(
    int unit0, int tid,
    const float* __restrict__ xt,
    const float* __restrict__ w_s,
    const float* __restrict__ bias_s,
    const float* __restrict__ hA,
    const float* __restrict__ hB,
    float* __restrict__ h_out,
    float* __restrict__ c_st,
    float* __restrict__ h2all,
    int nch,
    float* __restrict__ v0, float* __restrict__ v1, float* __restrict__ z_s)
{
    const int rp = tid & 7;           // row pair -> rows 2rp, 2rp+1
    const int ty = (tid >> 3) & 15;   // batch group
    const int tz = tid >> 7;          // k half
    const int b0 = ty * 8;

    unsigned long long a0=0,a1=0,a2=0,a3=0,a4=0,a5=0,a6=0,a7=0;

    stage_chunk(v0, 0, xt, hA, hB, tid);

    for (int c = 0; c < nch; ++c) {
        const int kk0 = c * 64;
        float* cur = (c & 1) ? v1 : v0;
        if (c + 1 < nch) {
            stage_chunk((c & 1) ? v0 : v1, kk0 + 64, xt, hA, hB, tid);
            asm volatile("cp.async.wait_group 1;" ::: "memory");
        } else {
            asm volatile("cp.async.wait_group 0;" ::: "memory");
        }
        __syncthreads();

        const float* wrow = w_s + (kk0 + tz * 32) * 16 + rp * 2;
        const float* vrow = cur + (tz * 32) * Bq + b0;
        #pragma unroll
        for (int k2 = 0; k2 < 32; ++k2) {
            float2 wv = *(const float2*)(wrow + k2 * 16);
            unsigned long long wp0 = pk2(wv.x), wp1 = pk2(wv.y);
            ulonglong2 p0 = *(const ulonglong2*)(vrow + k2 * Bq);
            ulonglong2 p1 = *(const ulonglong2*)(vrow + k2 * Bq + 4);
            fma2(a0, p0.x, wp0); fma2(a1, p0.y, wp0);
            fma2(a2, p1.x, wp0); fma2(a3, p1.y, wp0);
            fma2(a4, p0.x, wp1); fma2(a5, p0.y, wp1);
            fma2(a6, p1.x, wp1); fma2(a7, p1.y, wp1);
        }
        __syncthreads();   // buffer reuse guard (next stage writes this buffer)
    }

    // ---- split-K reduction into z_s [16][128] ----
    const int r0 = rp * 2, r1 = r0 + 1;
    float2 f;
    if (tz == 1) {
        f = up2(a0); z_s[r0*Bq+b0+0]=f.x; z_s[r0*Bq+b0+1]=f.y;
        f = up2(a1); z_s[r0*Bq+b0+2]=f.x; z_s[r0*Bq+b0+3]=f.y;
        f = up2(a2); z_s[r0*Bq+b0+4]=f.x; z_s[r0*Bq+b0+5]=f.y;
        f = up2(a3); z_s[r0*Bq+b0+6]=f.x; z_s[r0*Bq+b0+7]=f.y;
        f = up2(a4); z_s[r1*Bq+b0+0]=f.x; z_s[r1*Bq+b0+1]=f.y;
        f = up2(a5); z_s[r1*Bq+b0+2]=f.x; z_s[r1*Bq+b0+3]=f.y;
        f = up2(a6); z_s[r1*Bq+b0+4]=f.x; z_s[r1*Bq+b0+5]=f.y;
        f = up2(a7); z_s[r1*Bq+b0+6]=f.x; z_s[r1*Bq+b0+7]=f.y;
    }
    __syncthreads();
    if (tz == 0) {
        float bias0 = bias_s[r0];
        float bias1 = bias_s[r1];
        f = up2(a0); z_s[r0*Bq+b0+0]+=f.x+bias0; z_s[r0*Bq+b0+1]+=f.y+bias0;
        f = up2(a1); z_s[r0*Bq+b0+2]+=f.x+bias0; z_s[r0*Bq+b0+3]+=f.y+bias0;
        f = up2(a2); z_s[r0*Bq+b0+4]+=f.x+bias0; z_s[r0*Bq+b0+5]+=f.y+bias0;
        f = up2(a3); z_s[r0*Bq+b0+6]+=f.x+bias0; z_s[r0*Bq+b0+7]+=f.y+bias0;
        f = up2(a4); z_s[r1*Bq+b0+0]+=f.x+bias1; z_s[r1*Bq+b0+1]+=f.y+bias1;
        f = up2(a5); z_s[r1*Bq+b0+2]+=f.x+bias1; z_s[r1*Bq+b0+3]+=f.y+bias1;
        f = up2(a6); z_s[r1*Bq+b0+4]+=f.x+bias1; z_s[r1*Bq+b0+5]+=f.y+bias1;
        f = up2(a7); z_s[r1*Bq+b0+6]+=f.x+bias1; z_s[r1*Bq+b0+7]+=f.y+bias1;
    }
    __syncthreads();
    // ---- pointwise LSTM cell (4 units x 128 batch) ----
    #pragma unroll
    for (int it = 0; it < 2; ++it) {
        int idx = tid + it * 256;
        int au = idx >> 7;        // 0..3
        int b  = idx & 127;
        float zi = z_s[au*Bq+b], zf = z_s[(4+au)*Bq+b];
        float zg = z_s[(8+au)*Bq+b], zo = z_s[(12+au)*Bq+b];
        int j = unit0 + au;
        float cold = c_st[j * Bq + b];
        float cn = sigf(zf) * cold + sigf(zi) * tanhf(zg);
        float hn = sigf(zo) * tanhf(cn);
        c_st[j * Bq + b] = cn;
        h_out[j * Bq + b] = hn;
        if (h2all) h2all[j * Bq + b] = hn;
    }
}

// ---------------- attention phase: CTA handles batch b = blockIdx.x ----------------
__device__ __forceinline__ void attn_phase(
    int b, int tid,
    const float* __restrict__ W_abk, const float* __restrict__ b_abk,
    const float* __restrict__ c_seq, const float* __restrict__ h1,
    float* __restrict__ s)
{
    float* h_s   = s;           // 512
    float* abk_s = s + 512;     // 32
    float* al    = s + 544;     // 10
    float* be    = s + 556;     // 10
    float* ka    = s + 568;     // 10
    float* phi   = s + 584;     // 64

    #pragma unroll
    for (int k = tid; k < Hq; k += 256) h_s[k] = h1[k * Bq + b];
    __syncthreads();

    int lane = tid & 31, wrp = tid >> 5;
    for (int r = wrp; r < 3 * KWq; r += 8) {
        float sm = 0.f;
        const float* wr = W_abk + r * Hq;
        for (int k = lane; k < Hq; k += 32) sm += h_s[k] * wr[k];
        #pragma unroll
        for (int o = 16; o; o >>= 1) sm += __shfl_xor_sync(0xffffffffu, sm, o);
        if (lane == 0) abk_s[r] = sm + b_abk[r];
    }
    __syncthreads();
    if (tid < KWq) {
        float kap = g_kappa[b * KWq + tid] + expf(abk_s[2 * KWq + tid]);
        g_kappa[b * KWq + tid] = kap;
        al[tid] = expf(abk_s[tid]);
        be[tid] = expf(abk_s[KWq + tid]);
        ka[tid] = kap;
    }
    __syncthreads();
    if (tid < Uq) {
        float u = (float)tid;
        float sm = 0.f;
        #pragma unroll
        for (int k = 0; k < KWq; ++k) {
            float d = ka[k] - u;
            sm += al[k] * expf(-be[k] * d * d);
        }
        phi[tid] = sm;
    }
    __syncthreads();
    if (tid < Aq) {
        float sm = 0.f;
        for (int u = 0; u < Uq; ++u) sm += phi[u] * c_seq[(b * Uq + u) * Aq + tid];
        g_wp[tid * Bq + b] = sm;
    }
}

// ---------------- persistent main kernel ----------------
// smem (floats): w1[640*16] | w2[1152*16] | v[2*64*128] | z[16*128] | bs1[16] | bs2[16]
constexpr int SM_W1 = 0;
constexpr int SM_W2 = SM_W1 + 640 * 16;       // 10240
constexpr int SM_V0 = SM_W2 + 1152 * 16;      // 28672
constexpr int SM_V1 = SM_V0 + 64 * Bq;        // 36864
constexpr int SM_Z  = SM_V1 + 64 * Bq;        // 45056
constexpr int SM_B1 = SM_Z + 16 * Bq;         // 47104
constexpr int SM_B2 = SM_B1 + 16;             // 47120
constexpr int SM_TOT_FLOATS = SM_B2 + 16;     // 47136
constexpr int SM_BYTES = SM_TOT_FLOATS * 4;   // 188544

__global__ void __launch_bounds__(256, 1) k_main(
    const float* __restrict__ c_seq,
    const float* __restrict__ Wih1, const float* __restrict__ Whh1,
    const float* __restrict__ bih1, const float* __restrict__ bhh1,
    const float* __restrict__ Wih2, const float* __restrict__ Whh2,
    const float* __restrict__ bih2, const float* __restrict__ bhh2,
    const float* __restrict__ W_abk, const float* __restrict__ b_abk)
{
    extern __shared__ float smem[];
    float* w1_s = smem + SM_W1;
    float* w2_s = smem + SM_W2;
    float* v0   = smem + SM_V0;
    float* v1   = smem + SM_V1;
    float* z_s  = smem + SM_Z;
    float* bs1  = smem + SM_B1;
    float* bs2  = smem + SM_B2;

    const int tid = threadIdx.x;
    const int unit0 = blockIdx.x * 4;
    const int myb = blockIdx.x;

    // ---- one-time weight preload into smem (zero-padded per layout) ----
    for (int idx = tid; idx < 640 * 16; idx += 256) {
        int i = idx & 15, kk = idx >> 4;
        int r = ((i >> 2) * Hq) + unit0 + (i & 3);
        float wv = 0.f;
        if (kk < 3)                     wv = Wih1[r * 80 + kk];
        else if (kk >= 4 && kk < 81)    wv = Wih1[r * 80 + 3 + (kk - 4)];
        else if (kk >= 84 && kk < 596)  wv = Whh1[r * Hq + (kk - 84)];
        w1_s[idx] = wv;
    }
    for (int idx = tid; idx < 1152 * 16; idx += 256) {
        int i = idx & 15, kk = idx >> 4;
        int r = ((i >> 2) * Hq) + unit0 + (i & 3);
        float wv = 0.f;
        if (kk < 3)                      wv = Wih2[r * 592 + kk];
        else if (kk >= 4 && kk < 81)     wv = Wih2[r * 592 + 3 + (kk - 4)];
        else if (kk >= 84 && kk < 596)   wv = Wih2[r * 592 + 80 + (kk - 84)];
        else if (kk >= 596 && kk < 1108) wv = Whh2[r * Hq + (kk - 596)];
        w2_s[idx] = wv;
    }
    if (tid < 16) {
        int r = ((tid >> 2) * Hq) + unit0 + (tid & 3);
        bs1[tid] = bih1[r] + bhh1[r];
        bs2[tid] = bih2[r] + bhh2[r];
    }
    __syncthreads();

    for (int t = 0; t < Tq; ++t) {
        const int src = t & 1, dst = src ^ 1;
        // LSTM1: [x | w_{t-1} | h1_src]
        lstm_phase(unit0, tid, g_xT[t], w1_s, bs1,
                   g_h1[src], nullptr,
                   g_h1[dst], g_c1, nullptr,
                   10, v0, v1, z_s);
        grid_barrier();
        attn_phase(myb, tid, W_abk, b_abk, c_seq, g_h1[dst], z_s);
        grid_barrier();
        // LSTM2: [x | w_t | h1_new | h2_src]
        lstm_phase(unit0, tid, g_xT[t], w2_s, bs2,
                   g_h1[dst], g_h2[src],
                   g_h2[dst], g_c2, g_h2all[t],
                   18, v0, v1, z_s);
        __syncthreads();
        // No barrier needed before next LSTM1: it writes g_h1[src], which no
        // in-flight LSTM2(t) reads; all its reads were fenced at the two
        // barriers above.
    }
}

// ---------------- deferred fc2: grid (8 out-groups, 512 timesteps) ----------------
__global__ void __launch_bounds__(256) k_fc2(const float* __restrict__ Wf, const float* __restrict__ bf)
{
    __shared__ float v_s[64][Bq];
    __shared__ float w_s[64][16];
    const int tid = threadIdx.x;
    const int tx = tid & 15, ty = tid >> 4, b0 = ty * 8;
    const int t = blockIdx.y, og = blockIdx.x;
    const int o = og * 16 + tx;

    unsigned long long a0=0,a1=0,a2=0,a3=0;
    for (int c = 0; c < 8; ++c) {
        const int kk0 = c * 64;
        const float4* sp = (const float4*)(g_h2all[t] + kk0 * Bq);
        float4* dp = (float4*)(&v_s[0][0]);
        #pragma unroll
        for (int i = 0; i < 8; ++i) dp[tid + i * 256] = sp[tid + i * 256];
        {
            int i = tid & 15, kq = tid >> 4;
            int oo = og * 16 + i;
            float4 wv = make_float4(0.f, 0.f, 0.f, 0.f);
            if (oo < OUTq) wv = *(const float4*)(Wf + oo * Hq + kk0 + kq * 4);
            w_s[kq * 4 + 0][i] = wv.x; w_s[kq * 4 + 1][i] = wv.y;
            w_s[kq * 4 + 2][i] = wv.z; w_s[kq * 4 + 3][i] = wv.w;
        }
        __syncthreads();
        #pragma unroll
        for (int k = 0; k < 64; ++k) {
            unsigned long long wp = pk2(w_s[k][tx]);
            ulonglong2 p0 = *(const ulonglong2*)&v_s[k][b0];
            ulonglong2 p1 = *(const ulonglong2*)&v_s[k][b0 + 4];
            fma2(a0, p0.x, wp); fma2(a1, p0.y, wp);
            fma2(a2, p1.x, wp); fma2(a3, p1.y, wp);
        }
        __syncthreads();
    }
    if (o < OUTq) {
        float bias = bf[o];
        float* dstp = &g_raw[t][o * Bq + b0];
        float2 f;
        f = up2(a0); dstp[0] = f.x + bias; dstp[1] = f.y + bias;
        f = up2(a1); dstp[2] = f.x + bias; dstp[3] = f.y + bias;
        f = up2(a2); dstp[4] = f.x + bias; dstp[5] = f.y + bias;
        f = up2(a3); dstp[6] = f.x + bias; dstp[7] = f.y + bias;
    }
}

// ---------------- MDN post-processing -> d_out ----------------
__global__ void __launch_bounds__(256) k_post(float* __restrict__ out)
{
    int idx = blockIdx.x * 256 + threadIdx.x;
    if (idx >= Bq * Tq) return;
    int b = idx & (Bq - 1);
    int t = idx >> 7;
    const float* raw = g_raw[t];
    const size_t BT = (size_t)Bq * Tq;
    const size_t base = (size_t)b * Tq + t;

    float v[KMq];
    float m = -1e30f;
    #pragma unroll
    for (int k = 0; k < KMq; ++k) { v[k] = raw[k * Bq + b]; m = fmaxf(m, v[k]); }
    float s = 0.f;
    #pragma unroll
    for (int k = 0; k < KMq; ++k) { v[k] = expf(v[k] - m); s += v[k]; }
    float inv = 1.f / s;
    #pragma unroll
    for (int k = 0; k < KMq; ++k) out[base * KMq + k] = v[k] * inv;

    float* mu1 = out + BT * KMq;
    float* mu2 = out + 2 * BT * KMq;
    float* s1  = out + 3 * BT * KMq;
    float* s2  = out + 4 * BT * KMq;
    float* co  = out + 5 * BT * KMq;
    #pragma unroll
    for (int k = 0; k < KMq; ++k) {
        mu1[base * KMq + k] = raw[(KMq + k) * Bq + b];
        mu2[base * KMq + k] = raw[(2 * KMq + k) * Bq + b];
        s1[base * KMq + k]  = expf(raw[(3 * KMq + k) * Bq + b]);
        s2[base * KMq + k]  = expf(raw[(4 * KMq + k) * Bq + b]);
        co[base * KMq + k]  = tanhf(raw[(5 * KMq + k) * Bq + b]);
    }
    out[6 * BT * KMq + base] = sigf(raw[(6 * KMq) * Bq + b]);
}

// ---------------- launch ----------------
extern "C" void kernel_launch(void* const* d_in, const int* in_sizes, int n_in,
                              void* d_out, int out_size)
{
    (void)in_sizes; (void)n_in; (void)out_size;
    const float* x     = (const float*)d_in[0];
    const float* c_seq = (const float*)d_in[1];
    const float* Wih1  = (const float*)d_in[2];
    const float* Whh1  = (const float*)d_in[3];
    const float* bih1  = (const float*)d_in[4];
    const float* bhh1  = (const float*)d_in[5];
    const float* Wih2  = (const float*)d_in[6];
    const float* Whh2  = (const float*)d_in[7];
    const float* bih2  = (const float*)d_in[8];
    const float* bhh2  = (const float*)d_in[9];
    const float* W_abk = (const float*)d_in[10];
    const float* b_abk = (const float*)d_in[11];
    const float* W_fc2 = (const float*)d_in[12];
    const float* b_fc2 = (const float*)d_in[13];

    static bool attr_done = false;
    if (!attr_done) {
        cudaFuncSetAttribute(k_main, cudaFuncAttributeMaxDynamicSharedMemorySize, SM_BYTES);
        attr_done = true;
    }

    k_init<<<1024, 256>>>(x);
    k_main<<<NCTA, 256, SM_BYTES>>>(c_seq, Wih1, Whh1, bih1, bhh1,
                                    Wih2, Whh2, bih2, bhh2, W_abk, b_abk);
    k_fc2<<<dim3(8, Tq), 256>>>(W_fc2, b_fc2);
    k_post<<<256, 256>>>((float*)d_out);
}